// round 13
// baseline (speedup 1.0000x reference)
#include <cuda_runtime.h>
#include <cuda_bf16.h>
#include <cstdint>

// BoxCrop: crop -> aspect-preserving bilinear resize (long side = 336) -> pad(127)
// images: [64, 3, 768, 768] f32, boxes: [64, 4] i32 (XYWH), out: [64, 3, 336, 336] f32
// Per-image params precomputed; hot kernel = 1 px/thread (narrow gather span ->
// fewer L1 wavefronts per LDG), 12 batched gathers, factored weights.

#define O_SIZE   336
#define IMG_H    768
#define IMG_W    768
#define IMG_HW   (IMG_H * IMG_W)
#define FILL_V   127.0f
#define BATCH    64

__device__ int4   g_ip [BATCH];   // {pad_left, pad_top, new_w, new_h}
__device__ int4   g_ip2[BATCH];   // {xlo, xhi, ylo, yhi}
__device__ float4 g_fp [BATCH];   // {step_x, step_y, xb-0.5, yb-0.5}

__global__ void __launch_bounds__(BATCH) precompute_kernel(const int* __restrict__ boxes)
{
    const int b = threadIdx.x;
    const int4 box = __ldg((const int4*)boxes + b);
    const int xb = box.x, yb = box.y, wb = box.z, hb = box.w;
    const float wf = (float)wb;
    const float hf = (float)hb;

    // Exact fp32 matching JAX: scale = 336/max; round-half-even via rintf
    const float scale = 336.0f / fmaxf(wf, hf);
    const int new_w = (int)rintf(wf * scale);
    const int new_h = (int)rintf(hf * scale);
    const int pad_top  = (hb <  wb) ? (O_SIZE - new_h) / 2 : 0;
    const int pad_left = (hb >= wb) ? (O_SIZE - new_w) / 2 : 0;

    g_ip [b] = make_int4(pad_left, pad_top, new_w, new_h);
    g_ip2[b] = make_int4(xb, xb + wb - 1, yb, yb + hb - 1);
    g_fp [b] = make_float4(wf / (float)new_w, hf / (float)new_h,
                           (float)xb - 0.5f, (float)yb - 0.5f);
}

__global__ void __launch_bounds__(256) boxcrop_kernel(
    const float* __restrict__ images,
    float* __restrict__ out)
{
    const int b  = blockIdx.z;
    const int ox = blockIdx.x * blockDim.x + threadIdx.x;
    const int oy = blockIdx.y * blockDim.y + threadIdx.y;
    if (ox >= O_SIZE) return;

    // warp-uniform broadcast loads, L1/L2 resident
    const int4   ip  = __ldg(&g_ip [b]);
    const int4   ip2 = __ldg(&g_ip2[b]);
    const float4 fp  = __ldg(&g_fp [b]);

    float* outp = out + ((size_t)b * 3) * (O_SIZE * O_SIZE) + oy * O_SIZE + ox;
    const int cstride = O_SIZE * O_SIZE;

    const int iy = oy - ip.y;
    const int ix = ox - ip.x;

    if ((unsigned)iy >= (unsigned)ip.w || (unsigned)ix >= (unsigned)ip.z) {
        outp[0]           = FILL_V;
        outp[cstride]     = FILL_V;
        outp[2 * cstride] = FILL_V;
        return;
    }

    // ---- y side ----
    const float src_y = fp.w + ((float)iy + 0.5f) * fp.y;
    const float y0f = floorf(src_y);
    const float wy  = src_y - y0f;
    const int y0i = (int)y0f;
    const int y0 = min(max(y0i,     ip2.z), ip2.w);   // clamp from UNCLAMPED idx
    const int y1 = min(max(y0i + 1, ip2.z), ip2.w);
    const int r0 = y0 * IMG_W;
    const int r1 = y1 * IMG_W;

    // ---- x side ----
    const float src_x = fp.z + ((float)ix + 0.5f) * fp.x;
    const float x0f = floorf(src_x);
    const float wx  = src_x - x0f;
    const int x0i = (int)x0f;
    const int x0 = min(max(x0i,     ip2.x), ip2.y);
    const int x1 = min(max(x0i + 1, ip2.x), ip2.y);

    // factored 4-tap weights
    const float owx = 1.0f - wx;
    const float owy = 1.0f - wy;
    const float w00 = owx * owy, w01 = wx * owy;
    const float w10 = owx * wy,  w11 = wx * wy;

    const float* img = images + (size_t)b * 3 * IMG_HW;
    const float* p00 = img + r0 + x0;
    const float* p01 = img + r0 + x1;
    const float* p10 = img + r1 + x0;
    const float* p11 = img + r1 + x1;

    // ---- batch all 12 gathers (3 channels x 4 taps); channel stride immediate ----
    float v00[3], v01[3], v10[3], v11[3];
    #pragma unroll
    for (int c = 0; c < 3; c++) {
        v00[c] = __ldg(p00 + c * IMG_HW);
        v01[c] = __ldg(p01 + c * IMG_HW);
        v10[c] = __ldg(p10 + c * IMG_HW);
        v11[c] = __ldg(p11 + c * IMG_HW);
    }

    // ---- blend (1 MUL + 3 FMA per channel) + store ----
    #pragma unroll
    for (int c = 0; c < 3; c++) {
        float v = v00[c] * w00;
        v = fmaf(v01[c], w01, v);
        v = fmaf(v10[c], w10, v);
        v = fmaf(v11[c], w11, v);
        outp[c * cstride] = v;
    }
}

extern "C" void kernel_launch(void* const* d_in, const int* in_sizes, int n_in,
                              void* d_out, int out_size)
{
    const float* images = (const float*)d_in[0];
    const int*   boxes  = (const int*)d_in[1];
    float*       out    = (float*)d_out;

    precompute_kernel<<<1, BATCH>>>(boxes);

    dim3 block(32, 8, 1);
    dim3 grid((O_SIZE + 31) / 32, O_SIZE / 8, BATCH);   // 11 x 42 x 64
    boxcrop_kernel<<<grid, block>>>(images, out);
}